// round 10
// baseline (speedup 1.0000x reference)
#include <cuda_runtime.h>
#include <cuda_fp16.h>
#include <cstdint>
#include <cstddef>
#include <cstring>

#define S_SIZE 4096
#define IN_SZ  2048
#define KTOT   6144
#define BATCH  4096

// ---------------- scratch (device globals; no allocation APIs) ----------------
__device__ __half g_Zt[(size_t)BATCH * KTOT];           // [b][k] fp16 K-major
__device__ __half g_Z[4ull * S_SIZE * BATCH];           // preactivations fp16 [gate*S+m][n]

// ---------------- helpers ----------------
__device__ __forceinline__ uint32_t smem_u32(const void* p) {
    return (uint32_t)__cvta_generic_to_shared(p);
}

__device__ __forceinline__ uint32_t h2_u32(__half2 h) {
    uint32_t u;
    memcpy(&u, &h, 4);
    return u;
}

__device__ __forceinline__ void ldsm_x4(uint32_t& r0, uint32_t& r1, uint32_t& r2, uint32_t& r3,
                                        uint32_t addr) {
    asm volatile("ldmatrix.sync.aligned.m8n8.x4.shared.b16 {%0,%1,%2,%3}, [%4];"
                 : "=r"(r0), "=r"(r1), "=r"(r2), "=r"(r3) : "r"(addr));
}

__device__ __forceinline__ void mma16816(float* d, const uint32_t* a, const uint32_t* b) {
    asm volatile(
        "mma.sync.aligned.m16n8k16.row.col.f32.f16.f16.f32 "
        "{%0,%1,%2,%3}, {%4,%5,%6,%7}, {%8,%9}, {%0,%1,%2,%3};"
        : "+f"(d[0]), "+f"(d[1]), "+f"(d[2]), "+f"(d[3])
        : "r"(a[0]), "r"(a[1]), "r"(a[2]), "r"(a[3]), "r"(b[0]), "r"(b[1]));
}

__device__ __forceinline__ void sts_h4(uint32_t addr, uint32_t h0, uint32_t h1) {
    asm volatile("st.shared.v2.b32 [%0], {%1, %2};" :: "r"(addr), "r"(h0), "r"(h1) : "memory");
}

__device__ __forceinline__ float sigf(float x) { return 1.0f / (1.0f + __expf(-x)); }
__device__ __forceinline__ float tanh_(float x) { return 2.0f * sigf(2.0f * x) - 1.0f; }

// ---------------- convert acts (transpose to K-major fp16) ----------------
__global__ void convert_acts(const float* __restrict__ x, const float* __restrict__ h) {
    __shared__ float tile[32][33];
    const int kb = blockIdx.x * 32;
    const int bb = blockIdx.y * 32;
    const int tx = threadIdx.x, ty = threadIdx.y;   // 32 x 8
#pragma unroll
    for (int i = 0; i < 4; i++) {
        int k = kb + ty + i * 8;
        const float* src = (k < IN_SZ) ? (x + (size_t)k * BATCH)
                                       : (h + (size_t)(k - IN_SZ) * BATCH);
        tile[ty + i * 8][tx] = src[bb + tx];
    }
    __syncthreads();
#pragma unroll
    for (int i = 0; i < 4; i++) {
        int b = bb + ty + i * 8;
        int k = kb + tx;
        g_Zt[(size_t)b * KTOT + k] = __float2half_rn(tile[tx][ty + i * 8]);
    }
}

// ---------------- GEMM: Z[16384, 4096] = W[16384, 6144](fp32, on the fly) @ g_Zt^T ------------
// CTA 128x128, 128 threads, 4 warps 2(m) x 2(n), warp tile 64x64, occupancy 2.
// A loaded as fp32 directly from original weights (LDG->cvt->STS); B via cp.async fp16.
#define KBLK        64
#define NUM_IT      (KTOT / KBLK)        // 96
#define STAGE_BYTES 32768                // A fp16 16KB + B fp16 16KB
#define NSTAGE      3
#define SMEM_TOTAL  (NSTAGE * STAGE_BYTES)

// B fill: 1024 x 16B chunks, 128 threads -> 8 cp.async each, one commit group
__device__ __forceinline__ void fill_B(uint32_t bbase, const __half* Bg, int kblk, int tid) {
#pragma unroll
    for (int i = 0; i < 8; i++) {
        int id = i * 128 + tid;
        int r  = id >> 3;                // 0..127
        int c  = id & 7;
        const __half* src = Bg + (size_t)r * KTOT + kblk + c * 8;
        uint32_t dst = bbase + (uint32_t)r * 128u + (uint32_t)((c ^ (r & 7)) * 16);
        asm volatile("cp.async.cg.shared.global [%0], [%1], 16;\n"
                     :: "r"(dst), "l"(src) : "memory");
    }
    asm volatile("cp.async.commit_group;\n" ::: "memory");
}

// A fill (blocking, prologue only): fp32 source, stride in floats
__device__ __forceinline__ void fill_A_block(uint32_t abase, const float* asrc, size_t astride,
                                             int tid) {
#pragma unroll
    for (int i = 0; i < 16; i++) {
        int id = i * 128 + tid;
        int r  = id >> 4;                // 0..127
        int c4 = id & 15;                // float4 within row
        float4 v = *(const float4*)(asrc + (size_t)r * astride + c4 * 4);
        uint32_t h0 = h2_u32(__floats2half2_rn(v.x, v.y));
        uint32_t h1 = h2_u32(__floats2half2_rn(v.z, v.w));
        uint32_t addr = abase + (uint32_t)r * 128u
                      + (uint32_t)((((c4 >> 1) ^ (r & 7)) * 16) + (c4 & 1) * 8);
        sts_h4(addr, h0, h1);
    }
}

__global__ void __launch_bounds__(128, 2) lstm_gemm(
    const float* __restrict__ wf_in, const float* __restrict__ wf_h,
    const float* __restrict__ wi_in, const float* __restrict__ wi_h,
    const float* __restrict__ wc_in, const float* __restrict__ wc_h,
    const float* __restrict__ wo_in, const float* __restrict__ wo_h)
{
    extern __shared__ __align__(1024) char smem[];
    const uint32_t sb0 = smem_u32(smem);
    const int tid = threadIdx.x;
    const int wid = tid >> 5, l = tid & 31;
    const int wm = wid >> 1, wn = wid & 1;          // 2x2 warps, warp tile 64x64
    const int m0 = (int)blockIdx.y * 128;           // over 16384 (gate-stacked rows)
    const int n0 = (int)blockIdx.x * 128;           // over 4096
    const int gate  = m0 >> 12;
    const int srow0 = m0 & 4095;

    const float* w_in = (gate == 0) ? wf_in : (gate == 1) ? wi_in : (gate == 2) ? wc_in : wo_in;
    const float* w_h  = (gate == 0) ? wf_h  : (gate == 1) ? wi_h  : (gate == 2) ? wc_h  : wo_h;
    const __half* Bg  = g_Zt + (size_t)n0 * KTOT;

    int arow[4], brow[4];
#pragma unroll
    for (int t = 0; t < 4; t++)
        arow[t] = wm * 64 + t * 16 + (l & 7) + ((l >> 3) & 1) * 8;
#pragma unroll
    for (int p = 0; p < 4; p++)
        brow[p] = wn * 64 + p * 16 + (l & 7) + ((l >> 4) & 1) * 8;
    const int a_sel = (l >> 4) & 1;
    const int b_sel = (l >> 3) & 1;

    float acc[4][8][4];
#pragma unroll
    for (int t = 0; t < 4; t++)
#pragma unroll
        for (int p = 0; p < 8; p++)
#pragma unroll
            for (int q = 0; q < 4; q++) acc[t][p][q] = 0.0f;

    // prologue: stages 0 and 1 (A blocking LDG->STS, B cp.async)
    fill_B(sb0 + 16384u, Bg, 0, tid);
    fill_B(sb0 + STAGE_BYTES + 16384u, Bg, KBLK, tid);
    fill_A_block(sb0, w_in + (size_t)srow0 * IN_SZ, IN_SZ, tid);
    fill_A_block(sb0 + STAGE_BYTES, w_in + (size_t)srow0 * IN_SZ + KBLK, IN_SZ, tid);

    for (int it = 0; it < NUM_IT; it++) {
        if (it == NUM_IT - 1) asm volatile("cp.async.wait_group 0;\n" ::: "memory");
        else                  asm volatile("cp.async.wait_group 1;\n" ::: "memory");
        __syncthreads();

        const bool pf = (it + 2 < NUM_IT);
        const int kb2 = (it + 2) * KBLK;
        const float* asrc = nullptr;
        size_t astride = 0;
        uint32_t pstage = sb0 + (uint32_t)((it + 2) % NSTAGE) * STAGE_BYTES;
        if (pf) {
            if (kb2 < IN_SZ) { asrc = w_in + (size_t)srow0 * IN_SZ + kb2;            astride = IN_SZ; }
            else             { asrc = w_h  + (size_t)srow0 * S_SIZE + (kb2 - IN_SZ); astride = S_SIZE; }
            fill_B(pstage + 16384u, Bg, kb2, tid);
        }

        const uint32_t sa = sb0 + (uint32_t)(it % NSTAGE) * STAGE_BYTES;
        const uint32_t sbq = sa + 16384u;
#pragma unroll
        for (int ks = 0; ks < 4; ks++) {
            // issue A prefetch loads for group ks (consumed after this mma block)
            float4 v[4];
#pragma unroll
            for (int j = 0; j < 4; j++) {
                if (pf) {
                    int id = (ks * 4 + j) * 128 + tid;
                    int r = id >> 4, c4 = id & 15;
                    v[j] = *(const float4*)(asrc + (size_t)r * astride + c4 * 4);
                }
            }
            uint32_t a[4][4], b[4][4];
#pragma unroll
            for (int t = 0; t < 4; t++) {
                uint32_t addr = sa + (uint32_t)arow[t] * 128u
                              + (uint32_t)(((ks * 2 + a_sel) ^ (arow[t] & 7)) * 16);
                ldsm_x4(a[t][0], a[t][1], a[t][2], a[t][3], addr);
            }
#pragma unroll
            for (int p = 0; p < 4; p++) {
                uint32_t addr = sbq + (uint32_t)brow[p] * 128u
                              + (uint32_t)(((ks * 2 + b_sel) ^ (brow[p] & 7)) * 16);
                ldsm_x4(b[p][0], b[p][1], b[p][2], b[p][3], addr);
            }
#pragma unroll
            for (int t = 0; t < 4; t++)
#pragma unroll
                for (int p = 0; p < 8; p++)
                    mma16816(acc[t][p], a[t], &b[p >> 1][(p & 1) * 2]);
            // convert + store A group ks into prefetch stage
            if (pf) {
#pragma unroll
                for (int j = 0; j < 4; j++) {
                    int id = (ks * 4 + j) * 128 + tid;
                    int r = id >> 4, c4 = id & 15;
                    uint32_t h0 = h2_u32(__floats2half2_rn(v[j].x, v[j].y));
                    uint32_t h1 = h2_u32(__floats2half2_rn(v[j].z, v[j].w));
                    uint32_t addr = pstage + (uint32_t)r * 128u
                                  + (uint32_t)((((c4 >> 1) ^ (r & 7)) * 16) + (c4 & 1) * 8);
                    sts_h4(addr, h0, h1);
                }
            }
        }
    }

    // epilogue: write fp16 preactivations to g_Z
    const int g  = l >> 2;
    const int tg = l & 3;
#pragma unroll
    for (int t = 0; t < 4; t++) {
#pragma unroll
        for (int p = 0; p < 8; p++) {
            int row = m0 + wm * 64 + t * 16 + g;
            int col = n0 + wn * 64 + p * 8 + tg * 2;
            __half2* z0 = (__half2*)(g_Z + (size_t)row * BATCH + col);
            z0[0] = __floats2half2_rn(acc[t][p][0], acc[t][p][1]);
            __half2* z1 = (__half2*)(g_Z + (size_t)(row + 8) * BATCH + col);
            z1[0] = __floats2half2_rn(acc[t][p][2], acc[t][p][3]);
        }
    }
}

// ---------------- elementwise combine: 8 elems/thread ----------------
__global__ void lstm_elem(const float* __restrict__ prev_state,
                          const float* __restrict__ bf, const float* __restrict__ bi,
                          const float* __restrict__ bc, const float* __restrict__ bo,
                          float* __restrict__ out) {
    const size_t SB = (size_t)S_SIZE * BATCH;
    size_t i = (size_t)blockIdx.x * blockDim.x + threadIdx.x;
    size_t e = i * 8;
    if (e >= SB) return;
    int m = (int)(e >> 12);                 // BATCH = 4096; 8-groups never cross rows
    const float vbf = bf[m], vbi = bi[m], vbc = bc[m], vbo = bo[m];

    uint4 rf = *(const uint4*)(g_Z + e);
    uint4 ri = *(const uint4*)(g_Z + SB + e);
    uint4 rc = *(const uint4*)(g_Z + 2 * SB + e);
    uint4 ro = *(const uint4*)(g_Z + 3 * SB + e);
    float4 cp0 = *(const float4*)(prev_state + e);
    float4 cp1 = *(const float4*)(prev_state + e + 4);

    float zfv[8], ziv[8], zcv[8], zov[8], cpv[8], nsv[8], ov[8];
    const uint32_t* rfp = &rf.x; const uint32_t* rip = &ri.x;
    const uint32_t* rcp = &rc.x; const uint32_t* rop = &ro.x;
#pragma unroll
    for (int q = 0; q < 4; q++) {
        float2 f2;
        f2 = __half22float2(*(const __half2*)&rfp[q]); zfv[2*q] = f2.x; zfv[2*q+1] = f2.y;
        f2 = __half22float2(*(const __half2*)&rip[q]); ziv[2*q] = f2.x; ziv[2*q+1] = f2.y;
        f2 = __half22float2(*(const __half2*)&rcp[q]); zcv[2*q] = f2.x; zcv[2*q+1] = f2.y;
        f2 = __half22float2(*(const __half2*)&rop[q]); zov[2*q] = f2.x; zov[2*q+1] = f2.y;
    }
    cpv[0] = cp0.x; cpv[1] = cp0.y; cpv[2] = cp0.z; cpv[3] = cp0.w;
    cpv[4] = cp1.x; cpv[5] = cp1.y; cpv[6] = cp1.z; cpv[7] = cp1.w;
#pragma unroll
    for (int q = 0; q < 8; q++) {
        float f  = sigf(zfv[q] + vbf);
        float ig = sigf(ziv[q] + vbi);
        float ct = tanh_(zcv[q] + vbc);
        float og = sigf(zov[q] + vbo);
        float ns = cpv[q] * f + ig * ct;
        nsv[q] = ns;
        ov[q]  = tanh_(ns) * og;
    }
    *(float4*)(out + e)          = make_float4(nsv[0], nsv[1], nsv[2], nsv[3]);
    *(float4*)(out + e + 4)      = make_float4(nsv[4], nsv[5], nsv[6], nsv[7]);
    *(float4*)(out + SB + e)     = make_float4(ov[0], ov[1], ov[2], ov[3]);
    *(float4*)(out + SB + e + 4) = make_float4(ov[4], ov[5], ov[6], ov[7]);
}

// ---------------- host ----------------
extern "C" void kernel_launch(void* const* d_in, const int* in_sizes, int n_in,
                              void* d_out, int out_size) {
    const float* input      = (const float*)d_in[0];
    const float* prev_out   = (const float*)d_in[1];
    const float* prev_state = (const float*)d_in[2];
    const float* W_in_f = (const float*)d_in[3];
    const float* W_h_f  = (const float*)d_in[4];
    const float* b_f    = (const float*)d_in[5];
    const float* W_in_i = (const float*)d_in[6];
    const float* W_h_i  = (const float*)d_in[7];
    const float* b_i    = (const float*)d_in[8];
    const float* W_C_i  = (const float*)d_in[9];
    const float* W_C_h  = (const float*)d_in[10];
    const float* b_C    = (const float*)d_in[11];
    const float* W_in_o = (const float*)d_in[12];
    const float* W_h_o  = (const float*)d_in[13];
    const float* b_o    = (const float*)d_in[14];

    static bool attr_set = false;
    if (!attr_set) {
        cudaFuncSetAttribute(lstm_gemm, cudaFuncAttributeMaxDynamicSharedMemorySize, SMEM_TOTAL);
        attr_set = true;
    }

    convert_acts<<<dim3(KTOT / 32, BATCH / 32), dim3(32, 8)>>>(input, prev_out);
    lstm_gemm<<<dim3(BATCH / 128, 4 * S_SIZE / 128), 128, SMEM_TOTAL>>>(
        W_in_f, W_h_f, W_in_i, W_h_i, W_C_i, W_C_h, W_in_o, W_h_o);
    lstm_elem<<<(int)(((size_t)S_SIZE * BATCH / 8 + 255) / 256), 256>>>(
        prev_state, b_f, b_i, b_C, b_o, (float*)d_out);
}

// round 11
// speedup vs baseline: 1.7592x; 1.7592x over previous
#include <cuda_runtime.h>
#include <cuda_fp16.h>
#include <cstdint>
#include <cstddef>

#define S_SIZE 4096
#define IN_SZ  2048
#define KTOT   6144
#define BATCH  4096

// ---------------- scratch (device globals; no allocation APIs) ----------------
__device__ __half g_W[4ull * S_SIZE * KTOT];            // [gate][s][k] fp16 K-major (M-stacked)
__device__ __half g_Zt[(size_t)BATCH * KTOT];           // [b][k] fp16 K-major
__device__ __half g_Z[4ull * S_SIZE * BATCH];           // preactivations fp16

// ---------------- helpers ----------------
__device__ __forceinline__ uint32_t smem_u32(const void* p) {
    return (uint32_t)__cvta_generic_to_shared(p);
}

__device__ __forceinline__ void ldsm_x4(uint32_t& r0, uint32_t& r1, uint32_t& r2, uint32_t& r3,
                                        uint32_t addr) {
    asm volatile("ldmatrix.sync.aligned.m8n8.x4.shared.b16 {%0,%1,%2,%3}, [%4];"
                 : "=r"(r0), "=r"(r1), "=r"(r2), "=r"(r3) : "r"(addr));
}

__device__ __forceinline__ void mma16816(float* d, const uint32_t* a, const uint32_t* b) {
    asm volatile(
        "mma.sync.aligned.m16n8k16.row.col.f32.f16.f16.f32 "
        "{%0,%1,%2,%3}, {%4,%5,%6,%7}, {%8,%9}, {%0,%1,%2,%3};"
        : "+f"(d[0]), "+f"(d[1]), "+f"(d[2]), "+f"(d[3])
        : "r"(a[0]), "r"(a[1]), "r"(a[2]), "r"(a[3]), "r"(b[0]), "r"(b[1]));
}

__device__ __forceinline__ float sigf(float x) { return 1.0f / (1.0f + __expf(-x)); }
__device__ __forceinline__ float tanh_(float x) { return 2.0f * sigf(2.0f * x) - 1.0f; }

// ---------------- fused convert: weights (blocks [0, NWB)) + acts (rest) ----------------
#define NWB 4096
#define ACT_KB (KTOT / 32)               // 192

__global__ void convert_fused(const float* __restrict__ wf_in, const float* __restrict__ wf_h,
                              const float* __restrict__ wi_in, const float* __restrict__ wi_h,
                              const float* __restrict__ wc_in, const float* __restrict__ wc_h,
                              const float* __restrict__ wo_in, const float* __restrict__ wo_h,
                              const float* __restrict__ x, const float* __restrict__ h) {
    if (blockIdx.x < NWB) {
        // ---- weight packing ----
        const int per_gate4 = S_SIZE * (KTOT / 4);
        const int total4 = 4 * per_gate4;
        for (int t = blockIdx.x * blockDim.x + threadIdx.x; t < total4;
             t += NWB * blockDim.x) {
            int g = t / per_gate4;
            int rem = t - g * per_gate4;
            int s = rem / (KTOT / 4);
            int k = (rem - s * (KTOT / 4)) * 4;
            const float* win = (g == 0) ? wf_in : (g == 1) ? wi_in : (g == 2) ? wc_in : wo_in;
            const float* wh  = (g == 0) ? wf_h  : (g == 1) ? wi_h  : (g == 2) ? wc_h  : wo_h;
            float4 v;
            if (k < IN_SZ) v = *(const float4*)(win + (size_t)s * IN_SZ + k);
            else           v = *(const float4*)(wh  + (size_t)s * S_SIZE + (k - IN_SZ));
            __half2* dst = (__half2*)(g_W + (size_t)g * ((size_t)S_SIZE * KTOT)
                                          + (size_t)s * KTOT + k);
            dst[0] = __floats2half2_rn(v.x, v.y);
            dst[1] = __floats2half2_rn(v.z, v.w);
        }
    } else {
        // ---- activation transpose ----
        __shared__ float tile[32][33];
        const int bid = blockIdx.x - NWB;
        const int kb = (bid % ACT_KB) * 32;
        const int bb = (bid / ACT_KB) * 32;
        const int tx = threadIdx.x & 31;
        const int ty = threadIdx.x >> 5;            // 0..7
#pragma unroll
        for (int i = 0; i < 4; i++) {
            int k = kb + ty + i * 8;
            const float* src = (k < IN_SZ) ? (x + (size_t)k * BATCH)
                                           : (h + (size_t)(k - IN_SZ) * BATCH);
            tile[ty + i * 8][tx] = src[bb + tx];
        }
        __syncthreads();
#pragma unroll
        for (int i = 0; i < 4; i++) {
            int b = bb + ty + i * 8;
            int k = kb + tx;
            g_Zt[(size_t)b * KTOT + k] = __float2half_rn(tile[tx][ty + i * 8]);
        }
    }
}

// ---------------- GEMM: Z[16384, 4096] = g_W[16384, 6144] @ g_Zt[4096, 6144]^T ----------------
// CTA 128x128, 128 threads, 4 warps 2(m) x 2(n), warp tile 64x64. Occupancy 2.
#define KBLK        64
#define NUM_IT      (KTOT / KBLK)        // 96
#define STAGE_BYTES 32768                // A 128x64 fp16 (16KB) + B 128x64 fp16 (16KB)
#define NSTAGE      3
#define SMEM_TOTAL  (NSTAGE * STAGE_BYTES)

// 2048 x 16B chunks per stage, 128 threads -> 16 each
__device__ __forceinline__ void fill_stage(uint32_t sbase, const __half* Ag, const __half* Bg,
                                           int kblk, int tid) {
#pragma unroll
    for (int i = 0; i < 16; i++) {
        int id = i * 128 + tid;
        int op = id >> 10;               // 0 = A, 1 = B
        int r  = (id >> 3) & 127;
        int c  = id & 7;
        const __half* src = (op ? Bg : Ag) + (size_t)r * KTOT + kblk + c * 8;
        uint32_t dst = sbase + (uint32_t)op * 16384u + (uint32_t)r * 128u
                     + (uint32_t)((c ^ (r & 7)) * 16);
        asm volatile("cp.async.cg.shared.global [%0], [%1], 16;\n"
                     :: "r"(dst), "l"(src) : "memory");
    }
    asm volatile("cp.async.commit_group;\n" ::: "memory");
}

__global__ void __launch_bounds__(128, 2) lstm_gemm(void) {
    extern __shared__ __align__(1024) char smem[];
    const uint32_t sb0 = smem_u32(smem);
    const int tid = threadIdx.x;
    const int wid = tid >> 5, l = tid & 31;
    const int wm = wid >> 1, wn = wid & 1;          // 2x2 warps, warp tile 64x64
    const int m0 = (int)blockIdx.y * 128;           // over 16384
    const int n0 = (int)blockIdx.x * 128;           // over 4096

    const __half* Ag = g_W  + (size_t)m0 * KTOT;
    const __half* Bg = g_Zt + (size_t)n0 * KTOT;

    int arow[4], brow[4];
#pragma unroll
    for (int t = 0; t < 4; t++)
        arow[t] = wm * 64 + t * 16 + (l & 7) + ((l >> 3) & 1) * 8;
#pragma unroll
    for (int p = 0; p < 4; p++)
        brow[p] = wn * 64 + p * 16 + (l & 7) + ((l >> 4) & 1) * 8;
    const int a_sel = (l >> 4) & 1;
    const int b_sel = (l >> 3) & 1;

    float acc[4][8][4];
#pragma unroll
    for (int t = 0; t < 4; t++)
#pragma unroll
        for (int p = 0; p < 8; p++)
#pragma unroll
            for (int q = 0; q < 4; q++) acc[t][p][q] = 0.0f;

    fill_stage(sb0, Ag, Bg, 0, tid);
    fill_stage(sb0 + STAGE_BYTES, Ag, Bg, KBLK, tid);

    for (int it = 0; it < NUM_IT; it++) {
        if (it == NUM_IT - 1) asm volatile("cp.async.wait_group 0;\n" ::: "memory");
        else                  asm volatile("cp.async.wait_group 1;\n" ::: "memory");
        __syncthreads();
        // fill(it+2) targets stage (it-1)%3, whose reads finished before the sync above.
        if (it + 2 < NUM_IT)
            fill_stage(sb0 + (uint32_t)((it + 2) % NSTAGE) * STAGE_BYTES,
                       Ag, Bg, (it + 2) * KBLK, tid);
        const uint32_t sa = sb0 + (uint32_t)(it % NSTAGE) * STAGE_BYTES;
        const uint32_t sbq = sa + 16384u;
#pragma unroll
        for (int ks = 0; ks < 4; ks++) {
            uint32_t a[4][4], b[4][4];
#pragma unroll
            for (int t = 0; t < 4; t++) {
                uint32_t addr = sa + (uint32_t)arow[t] * 128u
                              + (uint32_t)(((ks * 2 + a_sel) ^ (arow[t] & 7)) * 16);
                ldsm_x4(a[t][0], a[t][1], a[t][2], a[t][3], addr);
            }
#pragma unroll
            for (int p = 0; p < 4; p++) {
                uint32_t addr = sbq + (uint32_t)brow[p] * 128u
                              + (uint32_t)(((ks * 2 + b_sel) ^ (brow[p] & 7)) * 16);
                ldsm_x4(b[p][0], b[p][1], b[p][2], b[p][3], addr);
            }
#pragma unroll
            for (int t = 0; t < 4; t++)
#pragma unroll
                for (int p = 0; p < 8; p++)
                    mma16816(acc[t][p], a[t], &b[p >> 1][(p & 1) * 2]);
        }
    }

    // epilogue: write fp16 preactivations to g_Z
    const int g  = l >> 2;
    const int tg = l & 3;
#pragma unroll
    for (int t = 0; t < 4; t++) {
#pragma unroll
        for (int p = 0; p < 8; p++) {
            int row = m0 + wm * 64 + t * 16 + g;
            int col = n0 + wn * 64 + p * 8 + tg * 2;
            __half2* z0 = (__half2*)(g_Z + (size_t)row * BATCH + col);
            z0[0] = __floats2half2_rn(acc[t][p][0], acc[t][p][1]);
            __half2* z1 = (__half2*)(g_Z + (size_t)(row + 8) * BATCH + col);
            z1[0] = __floats2half2_rn(acc[t][p][2], acc[t][p][3]);
        }
    }
}

// ---------------- elementwise combine: 8 elems/thread ----------------
__global__ void lstm_elem(const float* __restrict__ prev_state,
                          const float* __restrict__ bf, const float* __restrict__ bi,
                          const float* __restrict__ bc, const float* __restrict__ bo,
                          float* __restrict__ out) {
    const size_t SB = (size_t)S_SIZE * BATCH;
    size_t i = (size_t)blockIdx.x * blockDim.x + threadIdx.x;
    size_t e = i * 8;
    if (e >= SB) return;
    int m = (int)(e >> 12);                 // BATCH = 4096; 8-groups never cross rows
    const float vbf = bf[m], vbi = bi[m], vbc = bc[m], vbo = bo[m];

    uint4 rf = *(const uint4*)(g_Z + e);
    uint4 ri = *(const uint4*)(g_Z + SB + e);
    uint4 rc = *(const uint4*)(g_Z + 2 * SB + e);
    uint4 ro = *(const uint4*)(g_Z + 3 * SB + e);
    float4 cp0 = *(const float4*)(prev_state + e);
    float4 cp1 = *(const float4*)(prev_state + e + 4);

    float zfv[8], ziv[8], zcv[8], zov[8], cpv[8], nsv[8], ov[8];
    const uint32_t* rfp = &rf.x; const uint32_t* rip = &ri.x;
    const uint32_t* rcp = &rc.x; const uint32_t* rop = &ro.x;
#pragma unroll
    for (int q = 0; q < 4; q++) {
        float2 f2;
        f2 = __half22float2(*(const __half2*)&rfp[q]); zfv[2*q] = f2.x; zfv[2*q+1] = f2.y;
        f2 = __half22float2(*(const __half2*)&rip[q]); ziv[2*q] = f2.x; ziv[2*q+1] = f2.y;
        f2 = __half22float2(*(const __half2*)&rcp[q]); zcv[2*q] = f2.x; zcv[2*q+1] = f2.y;
        f2 = __half22float2(*(const __half2*)&rop[q]); zov[2*q] = f2.x; zov[2*q+1] = f2.y;
    }
    cpv[0] = cp0.x; cpv[1] = cp0.y; cpv[2] = cp0.z; cpv[3] = cp0.w;
    cpv[4] = cp1.x; cpv[5] = cp1.y; cpv[6] = cp1.z; cpv[7] = cp1.w;
#pragma unroll
    for (int q = 0; q < 8; q++) {
        float f  = sigf(zfv[q] + vbf);
        float ig = sigf(ziv[q] + vbi);
        float ct = tanh_(zcv[q] + vbc);
        float og = sigf(zov[q] + vbo);
        float ns = cpv[q] * f + ig * ct;
        nsv[q] = ns;
        ov[q]  = tanh_(ns) * og;
    }
    *(float4*)(out + e)          = make_float4(nsv[0], nsv[1], nsv[2], nsv[3]);
    *(float4*)(out + e + 4)      = make_float4(nsv[4], nsv[5], nsv[6], nsv[7]);
    *(float4*)(out + SB + e)     = make_float4(ov[0], ov[1], ov[2], ov[3]);
    *(float4*)(out + SB + e + 4) = make_float4(ov[4], ov[5], ov[6], ov[7]);
}

// ---------------- host ----------------
extern "C" void kernel_launch(void* const* d_in, const int* in_sizes, int n_in,
                              void* d_out, int out_size) {
    const float* input      = (const float*)d_in[0];
    const float* prev_out   = (const float*)d_in[1];
    const float* prev_state = (const float*)d_in[2];
    const float* W_in_f = (const float*)d_in[3];
    const float* W_h_f  = (const float*)d_in[4];
    const float* b_f    = (const float*)d_in[5];
    const float* W_in_i = (const float*)d_in[6];
    const float* W_h_i  = (const float*)d_in[7];
    const float* b_i    = (const float*)d_in[8];
    const float* W_C_i  = (const float*)d_in[9];
    const float* W_C_h  = (const float*)d_in[10];
    const float* b_C    = (const float*)d_in[11];
    const float* W_in_o = (const float*)d_in[12];
    const float* W_h_o  = (const float*)d_in[13];
    const float* b_o    = (const float*)d_in[14];

    static bool attr_set = false;
    if (!attr_set) {
        cudaFuncSetAttribute(lstm_gemm, cudaFuncAttributeMaxDynamicSharedMemorySize, SMEM_TOTAL);
        attr_set = true;
    }

    convert_fused<<<NWB + ACT_KB * (BATCH / 32), 256>>>(
        W_in_f, W_h_f, W_in_i, W_h_i, W_C_i, W_C_h, W_in_o, W_h_o, input, prev_out);
    lstm_gemm<<<dim3(BATCH / 128, 4 * S_SIZE / 128), 128, SMEM_TOTAL>>>();
    lstm_elem<<<(int)(((size_t)S_SIZE * BATCH / 8 + 255) / 256), 256>>>(
        prev_state, b_f, b_i, b_C, b_o, (float*)d_out);
}

// round 12
// speedup vs baseline: 1.7674x; 1.0047x over previous
#include <cuda_runtime.h>
#include <cuda_fp16.h>
#include <cstdint>
#include <cstddef>

#define S_SIZE 4096
#define IN_SZ  2048
#define KTOT   6144
#define BATCH  4096

// ---------------- scratch (device globals; no allocation APIs) ----------------
__device__ __half g_W[4ull * S_SIZE * KTOT];            // [gate][s][k] fp16 K-major (M-stacked)
__device__ __half g_Zt[(size_t)BATCH * KTOT];           // [b][k] fp16 K-major
__device__ __half g_Z[4ull * S_SIZE * BATCH];           // preactivations fp16

// ---------------- helpers ----------------
__device__ __forceinline__ uint32_t smem_u32(const void* p) {
    return (uint32_t)__cvta_generic_to_shared(p);
}

__device__ __forceinline__ void ldsm_x4(uint32_t& r0, uint32_t& r1, uint32_t& r2, uint32_t& r3,
                                        uint32_t addr) {
    asm volatile("ldmatrix.sync.aligned.m8n8.x4.shared.b16 {%0,%1,%2,%3}, [%4];"
                 : "=r"(r0), "=r"(r1), "=r"(r2), "=r"(r3) : "r"(addr));
}

__device__ __forceinline__ void mma16816(float* d, const uint32_t* a, const uint32_t* b) {
    asm volatile(
        "mma.sync.aligned.m16n8k16.row.col.f32.f16.f16.f32 "
        "{%0,%1,%2,%3}, {%4,%5,%6,%7}, {%8,%9}, {%0,%1,%2,%3};"
        : "+f"(d[0]), "+f"(d[1]), "+f"(d[2]), "+f"(d[3])
        : "r"(a[0]), "r"(a[1]), "r"(a[2]), "r"(a[3]), "r"(b[0]), "r"(b[1]));
}

__device__ __forceinline__ float sigf(float x) { return 1.0f / (1.0f + __expf(-x)); }
__device__ __forceinline__ float tanh_(float x) { return 2.0f * sigf(2.0f * x) - 1.0f; }

// ---------------- fused convert: weights (blocks [0, NWB)) + acts (rest) ----------------
#define NWB 4096
#define ACT_KB (KTOT / 32)               // 192

__global__ void convert_fused(const float* __restrict__ wf_in, const float* __restrict__ wf_h,
                              const float* __restrict__ wi_in, const float* __restrict__ wi_h,
                              const float* __restrict__ wc_in, const float* __restrict__ wc_h,
                              const float* __restrict__ wo_in, const float* __restrict__ wo_h,
                              const float* __restrict__ x, const float* __restrict__ h) {
    if (blockIdx.x < NWB) {
        // ---- weight packing: 8 k-elems per step (2x float4 load, 1x uint4 store) ----
        const int per_gate8 = S_SIZE * (KTOT / 8);          // 4096*768 = 3145728
        const int total8 = 4 * per_gate8;
        const int nthr = NWB * 256;
        for (int t = blockIdx.x * blockDim.x + threadIdx.x; t < total8; t += nthr) {
            int g   = t >> 21;                              // t / per_gate8 (2^21 = 3145728... no)
            // per_gate8 = 3145728 = 3 * 2^20; do it with one division (compiler folds to mul)
            g = t / per_gate8;
            int rem = t - g * per_gate8;
            int s = rem / (KTOT / 8);                       // /768
            int k = (rem - s * (KTOT / 8)) * 8;
            const float* win = (g == 0) ? wf_in : (g == 1) ? wi_in : (g == 2) ? wc_in : wo_in;
            const float* wh  = (g == 0) ? wf_h  : (g == 1) ? wi_h  : (g == 2) ? wc_h  : wo_h;
            float4 v0, v1;
            if (k < IN_SZ) {
                const float* p = win + (size_t)s * IN_SZ + k;
                v0 = *(const float4*)p;
                v1 = *(const float4*)(p + 4);
            } else {
                const float* p = wh + (size_t)s * S_SIZE + (k - IN_SZ);
                v0 = *(const float4*)p;
                v1 = *(const float4*)(p + 4);
            }
            __half2 h0 = __floats2half2_rn(v0.x, v0.y);
            __half2 h1 = __floats2half2_rn(v0.z, v0.w);
            __half2 h2 = __floats2half2_rn(v1.x, v1.y);
            __half2 h3 = __floats2half2_rn(v1.z, v1.w);
            uint4 pack;
            pack.x = *(uint32_t*)&h0; pack.y = *(uint32_t*)&h1;
            pack.z = *(uint32_t*)&h2; pack.w = *(uint32_t*)&h3;
            *(uint4*)(g_W + (size_t)g * ((size_t)S_SIZE * KTOT) + (size_t)s * KTOT + k) = pack;
        }
    } else {
        // ---- activation transpose ----
        __shared__ float tile[32][33];
        const int bid = blockIdx.x - NWB;
        const int kb = (bid % ACT_KB) * 32;
        const int bb = (bid / ACT_KB) * 32;
        const int tx = threadIdx.x & 31;
        const int ty = threadIdx.x >> 5;            // 0..7
#pragma unroll
        for (int i = 0; i < 4; i++) {
            int k = kb + ty + i * 8;
            const float* src = (k < IN_SZ) ? (x + (size_t)k * BATCH)
                                           : (h + (size_t)(k - IN_SZ) * BATCH);
            tile[ty + i * 8][tx] = src[bb + tx];
        }
        __syncthreads();
#pragma unroll
        for (int i = 0; i < 4; i++) {
            int b = bb + ty + i * 8;
            int k = kb + tx;
            g_Zt[(size_t)b * KTOT + k] = __float2half_rn(tile[tx][ty + i * 8]);
        }
    }
}

// ---------------- GEMM: Z[16384, 4096] = g_W[16384, 6144] @ g_Zt[4096, 6144]^T ----------------
// CTA 128x128, 128 threads, 4 warps 2(m) x 2(n), warp tile 64x64. Occupancy 2.
#define KBLK        64
#define NUM_IT      (KTOT / KBLK)        // 96
#define STAGE_BYTES 32768                // A 128x64 fp16 (16KB) + B 128x64 fp16 (16KB)
#define NSTAGE      3
#define SMEM_TOTAL  (NSTAGE * STAGE_BYTES)

// 2048 x 16B chunks per stage, 128 threads -> 16 each
__device__ __forceinline__ void fill_stage(uint32_t sbase, const __half* Ag, const __half* Bg,
                                           int kblk, int tid) {
#pragma unroll
    for (int i = 0; i < 16; i++) {
        int id = i * 128 + tid;
        int op = id >> 10;               // 0 = A, 1 = B
        int r  = (id >> 3) & 127;
        int c  = id & 7;
        const __half* src = (op ? Bg : Ag) + (size_t)r * KTOT + kblk + c * 8;
        uint32_t dst = sbase + (uint32_t)op * 16384u + (uint32_t)r * 128u
                     + (uint32_t)((c ^ (r & 7)) * 16);
        asm volatile("cp.async.cg.shared.global [%0], [%1], 16;\n"
                     :: "r"(dst), "l"(src) : "memory");
    }
    asm volatile("cp.async.commit_group;\n" ::: "memory");
}

__global__ void __launch_bounds__(128, 2) lstm_gemm(void) {
    extern __shared__ __align__(1024) char smem[];
    const uint32_t sb0 = smem_u32(smem);
    const int tid = threadIdx.x;
    const int wid = tid >> 5, l = tid & 31;
    const int wm = wid >> 1, wn = wid & 1;          // 2x2 warps, warp tile 64x64
    const int m0 = (int)blockIdx.y * 128;           // over 16384
    const int n0 = (int)blockIdx.x * 128;           // over 4096

    const __half* Ag = g_W  + (size_t)m0 * KTOT;
    const __half* Bg = g_Zt + (size_t)n0 * KTOT;

    int arow[4], brow[4];
#pragma unroll
    for (int t = 0; t < 4; t++)
        arow[t] = wm * 64 + t * 16 + (l & 7) + ((l >> 3) & 1) * 8;
#pragma unroll
    for (int p = 0; p < 4; p++)
        brow[p] = wn * 64 + p * 16 + (l & 7) + ((l >> 4) & 1) * 8;
    const int a_sel = (l >> 4) & 1;
    const int b_sel = (l >> 3) & 1;

    float acc[4][8][4];
#pragma unroll
    for (int t = 0; t < 4; t++)
#pragma unroll
        for (int p = 0; p < 8; p++)
#pragma unroll
            for (int q = 0; q < 4; q++) acc[t][p][q] = 0.0f;

    fill_stage(sb0, Ag, Bg, 0, tid);
    fill_stage(sb0 + STAGE_BYTES, Ag, Bg, KBLK, tid);

    for (int it = 0; it < NUM_IT; it++) {
        if (it == NUM_IT - 1) asm volatile("cp.async.wait_group 0;\n" ::: "memory");
        else                  asm volatile("cp.async.wait_group 1;\n" ::: "memory");
        __syncthreads();
        // fill(it+2) targets stage (it-1)%3, whose reads finished before the sync above.
        if (it + 2 < NUM_IT)
            fill_stage(sb0 + (uint32_t)((it + 2) % NSTAGE) * STAGE_BYTES,
                       Ag, Bg, (it + 2) * KBLK, tid);
        const uint32_t sa = sb0 + (uint32_t)(it % NSTAGE) * STAGE_BYTES;
        const uint32_t sbq = sa + 16384u;
#pragma unroll
        for (int ks = 0; ks < 4; ks++) {
            uint32_t a[4][4], b[4][4];
#pragma unroll
            for (int t = 0; t < 4; t++) {
                uint32_t addr = sa + (uint32_t)arow[t] * 128u
                              + (uint32_t)(((ks * 2 + a_sel) ^ (arow[t] & 7)) * 16);
                ldsm_x4(a[t][0], a[t][1], a[t][2], a[t][3], addr);
            }
#pragma unroll
            for (int p = 0; p < 4; p++) {
                uint32_t addr = sbq + (uint32_t)brow[p] * 128u
                              + (uint32_t)(((ks * 2 + b_sel) ^ (brow[p] & 7)) * 16);
                ldsm_x4(b[p][0], b[p][1], b[p][2], b[p][3], addr);
            }
#pragma unroll
            for (int t = 0; t < 4; t++)
#pragma unroll
                for (int p = 0; p < 8; p++)
                    mma16816(acc[t][p], a[t], &b[p >> 1][(p & 1) * 2]);
        }
    }

    // epilogue: write fp16 preactivations to g_Z
    const int g  = l >> 2;
    const int tg = l & 3;
#pragma unroll
    for (int t = 0; t < 4; t++) {
#pragma unroll
        for (int p = 0; p < 8; p++) {
            int row = m0 + wm * 64 + t * 16 + g;
            int col = n0 + wn * 64 + p * 8 + tg * 2;
            __half2* z0 = (__half2*)(g_Z + (size_t)row * BATCH + col);
            z0[0] = __floats2half2_rn(acc[t][p][0], acc[t][p][1]);
            __half2* z1 = (__half2*)(g_Z + (size_t)(row + 8) * BATCH + col);
            z1[0] = __floats2half2_rn(acc[t][p][2], acc[t][p][3]);
        }
    }
}

// ---------------- elementwise combine: 8 elems/thread ----------------
__global__ void lstm_elem(const float* __restrict__ prev_state,
                          const float* __restrict__ bf, const float* __restrict__ bi,
                          const float* __restrict__ bc, const float* __restrict__ bo,
                          float* __restrict__ out) {
    const size_t SB = (size_t)S_SIZE * BATCH;
    size_t i = (size_t)blockIdx.x * blockDim.x + threadIdx.x;
    size_t e = i * 8;
    if (e >= SB) return;
    int m = (int)(e >> 12);                 // BATCH = 4096; 8-groups never cross rows
    const float vbf = bf[m], vbi = bi[m], vbc = bc[m], vbo = bo[m];

    uint4 rf = *(const uint4*)(g_Z + e);
    uint4 ri = *(const uint4*)(g_Z + SB + e);
    uint4 rc = *(const uint4*)(g_Z + 2 * SB + e);
    uint4 ro = *(const uint4*)(g_Z + 3 * SB + e);
    float4 cp0 = *(const float4*)(prev_state + e);
    float4 cp1 = *(const float4*)(prev_state + e + 4);

    float zfv[8], ziv[8], zcv[8], zov[8], cpv[8], nsv[8], ov[8];
    const uint32_t* rfp = &rf.x; const uint32_t* rip = &ri.x;
    const uint32_t* rcp = &rc.x; const uint32_t* rop = &ro.x;
#pragma unroll
    for (int q = 0; q < 4; q++) {
        float2 f2;
        f2 = __half22float2(*(const __half2*)&rfp[q]); zfv[2*q] = f2.x; zfv[2*q+1] = f2.y;
        f2 = __half22float2(*(const __half2*)&rip[q]); ziv[2*q] = f2.x; ziv[2*q+1] = f2.y;
        f2 = __half22float2(*(const __half2*)&rcp[q]); zcv[2*q] = f2.x; zcv[2*q+1] = f2.y;
        f2 = __half22float2(*(const __half2*)&rop[q]); zov[2*q] = f2.x; zov[2*q+1] = f2.y;
    }
    cpv[0] = cp0.x; cpv[1] = cp0.y; cpv[2] = cp0.z; cpv[3] = cp0.w;
    cpv[4] = cp1.x; cpv[5] = cp1.y; cpv[6] = cp1.z; cpv[7] = cp1.w;
#pragma unroll
    for (int q = 0; q < 8; q++) {
        float f  = sigf(zfv[q] + vbf);
        float ig = sigf(ziv[q] + vbi);
        float ct = tanh_(zcv[q] + vbc);
        float og = sigf(zov[q] + vbo);
        float ns = cpv[q] * f + ig * ct;
        nsv[q] = ns;
        ov[q]  = tanh_(ns) * og;
    }
    *(float4*)(out + e)          = make_float4(nsv[0], nsv[1], nsv[2], nsv[3]);
    *(float4*)(out + e + 4)      = make_float4(nsv[4], nsv[5], nsv[6], nsv[7]);
    *(float4*)(out + SB + e)     = make_float4(ov[0], ov[1], ov[2], ov[3]);
    *(float4*)(out + SB + e + 4) = make_float4(ov[4], ov[5], ov[6], ov[7]);
}

// ---------------- host ----------------
extern "C" void kernel_launch(void* const* d_in, const int* in_sizes, int n_in,
                              void* d_out, int out_size) {
    const float* input      = (const float*)d_in[0];
    const float* prev_out   = (const float*)d_in[1];
    const float* prev_state = (const float*)d_in[2];
    const float* W_in_f = (const float*)d_in[3];
    const float* W_h_f  = (const float*)d_in[4];
    const float* b_f    = (const float*)d_in[5];
    const float* W_in_i = (const float*)d_in[6];
    const float* W_h_i  = (const float*)d_in[7];
    const float* b_i    = (const float*)d_in[8];
    const float* W_C_i  = (const float*)d_in[9];
    const float* W_C_h  = (const float*)d_in[10];
    const float* b_C    = (const float*)d_in[11];
    const float* W_in_o = (const float*)d_in[12];
    const float* W_h_o  = (const float*)d_in[13];
    const float* b_o    = (const float*)d_in[14];

    static bool attr_set = false;
    if (!attr_set) {
        cudaFuncSetAttribute(lstm_gemm, cudaFuncAttributeMaxDynamicSharedMemorySize, SMEM_TOTAL);
        attr_set = true;
    }

    convert_fused<<<NWB + ACT_KB * (BATCH / 32), 256>>>(
        W_in_f, W_h_f, W_in_i, W_h_i, W_C_i, W_C_h, W_in_o, W_h_o, input, prev_out);
    lstm_gemm<<<dim3(BATCH / 128, 4 * S_SIZE / 128), 128, SMEM_TOTAL>>>();
    lstm_elem<<<(int)(((size_t)S_SIZE * BATCH / 8 + 255) / 256), 256>>>(
        prev_state, b_f, b_i, b_C, b_o, (float*)d_out);
}